// round 8
// baseline (speedup 1.0000x reference)
#include <cuda_runtime.h>
#include <cuda_fp16.h>
#include <cstdint>

#define K_DIM 4096
#define N_DIM 4096
#define BM 128
#define BN 256
#define BK 64                        // halfs of K per stage
#define KT (K_DIM / BK)              // 64
#define STAGES 3
#define SROWB 144                    // bytes per smem row (odd*16 -> LDSM conflict-free)
#define A_BYTES (BM * SROWB)         // 18432
#define B_BYTES (BN * SROWB)         // 36864
#define STAGE_BYTES (A_BYTES + B_BYTES)
#define SMEM_BYTES (STAGES * STAGE_BYTES)   // 165888

// device-global scratch (allocation-free)
__device__ __half g_qwh[(size_t)N_DIM * K_DIM];          // 32 MB
__device__ __half g_xh[(size_t)16384 * K_DIM];           // 128 MB

// ---------------------------------------------------------------------------
// Kernel 1: qw transform -> fp16
// ---------------------------------------------------------------------------
__global__ void qw_kernel(const float4* __restrict__ w,
                          const float* __restrict__ alpha,
                          const int4* __restrict__ wc,
                          __half2* __restrict__ out) {
    size_t i = (size_t)blockIdx.x * blockDim.x + threadIdx.x;
    const size_t n4 = (size_t)N_DIM * K_DIM / 4;
    if (i >= n4) return;
    const float a = alpha[0];
    const float decay = expf(-0.001f);
    float4 wv = w[i];
    int4 cv = wc[i];
    float wa[4] = {wv.x, wv.y, wv.z, wv.w};
    int ca[4] = {cv.x, cv.y, cv.z, cv.w};
    float r[4];
#pragma unroll
    for (int j = 0; j < 4; j++) {
        float tv = 4.5f * (1.0f + wa[j] * a);
        // nearest of {3.5,4.0,4.5,5.0,5.5}; tie -> lower index (argmin-first)
        int idx = (tv > 3.75f) + (tv > 4.25f) + (tv > 4.75f) + (tv > 5.25f);
        float qv = 3.5f + 0.5f * (float)idx;
        float q = (qv / 4.5f - 1.0f) / a;
        q *= decay;
        float d = (float)ca[j];
        d = d / 1e8f * 0.1f;
        d = fminf(fmaxf(d, 0.0f), 0.5f);
        r[j] = q * (1.0f - d);
    }
    out[i * 2]     = __floats2half2_rn(r[0], r[1]);
    out[i * 2 + 1] = __floats2half2_rn(r[2], r[3]);
}

// ---------------------------------------------------------------------------
// Kernel 2: x -> fp16
// ---------------------------------------------------------------------------
__global__ void xh_kernel(const float4* __restrict__ x, __half2* __restrict__ out,
                          size_t n4) {
    size_t i = (size_t)blockIdx.x * blockDim.x + threadIdx.x;
    if (i >= n4) return;
    float4 v = x[i];
    out[i * 2]     = __floats2half2_rn(v.x, v.y);
    out[i * 2 + 1] = __floats2half2_rn(v.z, v.w);
}

// ---------------------------------------------------------------------------
// Kernel 3: y[M,N] = xh[M,K] @ qwh[N,K]^T   fp16 mma.sync m16n8k16
// 128x256 CTA tile, 256 threads (8 warps of 64x64), 3-stage BK=64
// ---------------------------------------------------------------------------
__device__ __forceinline__ void ldsm4(uint32_t* r, uint32_t addr) {
    asm volatile("ldmatrix.sync.aligned.m8n8.x4.shared.b16 {%0,%1,%2,%3}, [%4];"
                 : "=r"(r[0]), "=r"(r[1]), "=r"(r[2]), "=r"(r[3]) : "r"(addr));
}

__global__ __launch_bounds__(256, 1)
void gemm_fp16(const __half* __restrict__ A, const __half* __restrict__ B,
               float* __restrict__ Y) {
    extern __shared__ char smem[];
    const uint32_t sbase = (uint32_t)__cvta_generic_to_shared(smem);
    const int tid   = threadIdx.x;
    const int lane  = tid & 31;
    const int warp  = tid >> 5;
    const int warpM = warp >> 2;          // 0..1 -> 64-row band
    const int warpN = warp & 3;           // 0..3 -> 64-col band
    const int mBase = blockIdx.y * BM;
    const int nBase = blockIdx.x * BN;

    const __half* gA = A + (size_t)mBase * K_DIM;
    const __half* gB = B + (size_t)nBase * K_DIM;

    // cp.async mapping: A 1024 + B 2048 16B-chunks per stage; 12 per thread
    const int ldRow = tid >> 3;           // 0..31 (+32*i)
    const int ldC16 = tid & 7;            // 16B unit within 128B row data

    // fragment base offsets (bytes within stage) — same lane math as R7 (validated)
    const uint32_t aFrag = (uint32_t)((warpM * 64 + (lane & 15)) * SROWB
                                      + ((lane >> 4) & 1) * 16);
    const uint32_t bFrag = (uint32_t)(A_BYTES
                                      + (warpN * 64 + ((lane & 7) | ((lane >> 1) & 8))) * SROWB
                                      + ((lane >> 3) & 1) * 16);

    auto prefetch = [&](int t) {
        if (t < KT) {
            const uint32_t s = sbase + (t % STAGES) * STAGE_BYTES;
            const __half* gAk = gA + t * BK;
            const __half* gBk = gB + t * BK;
#pragma unroll
            for (int i = 0; i < 4; i++) {
                int row = ldRow + i * 32;
                asm volatile("cp.async.cg.shared.global [%0], [%1], 16;"
                             :: "r"(s + row * SROWB + ldC16 * 16),
                                "l"((const char*)(gAk + (size_t)row * K_DIM) + ldC16 * 16));
            }
#pragma unroll
            for (int i = 0; i < 8; i++) {
                int row = ldRow + i * 32;
                asm volatile("cp.async.cg.shared.global [%0], [%1], 16;"
                             :: "r"(s + A_BYTES + row * SROWB + ldC16 * 16),
                                "l"((const char*)(gBk + (size_t)row * K_DIM) + ldC16 * 16));
            }
        }
        asm volatile("cp.async.commit_group;");
    };

    float c[4][8][4];
#pragma unroll
    for (int i = 0; i < 4; i++)
#pragma unroll
        for (int j = 0; j < 8; j++)
#pragma unroll
            for (int r = 0; r < 4; r++) c[i][j][r] = 0.0f;

    prefetch(0); prefetch(1);

    for (int kt = 0; kt < KT; kt++) {
        asm volatile("cp.async.wait_group 1;");
        __syncthreads();
        prefetch(kt + 2);

        const uint32_t s = sbase + (kt % STAGES) * STAGE_BYTES;
#pragma unroll
        for (int ks = 0; ks < 4; ks++) {
            const uint32_t kb = ks * 32;        // 16 halves of K per step
            uint32_t a[4][4], b[4][4];
#pragma unroll
            for (int mt = 0; mt < 4; mt++)
                ldsm4(a[mt], s + aFrag + mt * (16 * SROWB) + kb);
#pragma unroll
            for (int np = 0; np < 4; np++)
                ldsm4(b[np], s + bFrag + np * (16 * SROWB) + kb);
#pragma unroll
            for (int mt = 0; mt < 4; mt++)
#pragma unroll
                for (int nt = 0; nt < 8; nt++) {
                    uint32_t b0 = b[nt >> 1][(nt & 1) * 2];
                    uint32_t b1 = b[nt >> 1][(nt & 1) * 2 + 1];
                    asm volatile(
                        "mma.sync.aligned.m16n8k16.row.col.f32.f16.f16.f32 "
                        "{%0,%1,%2,%3}, {%4,%5,%6,%7}, {%8,%9}, {%0,%1,%2,%3};"
                        : "+f"(c[mt][nt][0]), "+f"(c[mt][nt][1]),
                          "+f"(c[mt][nt][2]), "+f"(c[mt][nt][3])
                        : "r"(a[mt][0]), "r"(a[mt][1]), "r"(a[mt][2]), "r"(a[mt][3]),
                          "r"(b0), "r"(b1));
                }
        }
    }

    // epilogue
#pragma unroll
    for (int mt = 0; mt < 4; mt++) {
        const int r0 = mBase + warpM * 64 + mt * 16 + (lane >> 2);
#pragma unroll
        for (int nt = 0; nt < 8; nt++) {
            const int col = nBase + warpN * 64 + nt * 8 + (lane & 3) * 2;
            *(float2*)(Y + (size_t)r0 * N_DIM + col) =
                make_float2(c[mt][nt][0], c[mt][nt][1]);
            *(float2*)(Y + (size_t)(r0 + 8) * N_DIM + col) =
                make_float2(c[mt][nt][2], c[mt][nt][3]);
        }
    }
}

// ---------------------------------------------------------------------------
// Launch
// ---------------------------------------------------------------------------
extern "C" void kernel_launch(void* const* d_in, const int* in_sizes, int n_in,
                              void* d_out, int out_size) {
    const float* x     = (const float*)d_in[0];   // [8,2048,4096] fp32
    const float* w     = (const float*)d_in[1];   // [4096,4096] fp32
    const float* alpha = (const float*)d_in[2];   // [1] fp32
    const int*   wc    = (const int*)d_in[3];     // [4096,4096] int32
    float*       y     = (float*)d_out;           // [8,2048,4096] fp32

    const int M = in_sizes[0] / K_DIM;            // 16384

    __half *qwh = nullptr, *xh = nullptr;
    cudaGetSymbolAddress((void**)&qwh, g_qwh);
    cudaGetSymbolAddress((void**)&xh, g_xh);

    {   // qw transform -> fp16
        const size_t n4 = (size_t)N_DIM * K_DIM / 4;
        qw_kernel<<<(int)((n4 + 255) / 256), 256>>>(
            (const float4*)w, alpha, (const int4*)wc, (__half2*)qwh);
    }
    {   // x -> fp16
        const size_t n4 = (size_t)M * K_DIM / 4;
        xh_kernel<<<(int)((n4 + 255) / 256), 256>>>(
            (const float4*)x, (__half2*)xh, n4);
    }

    cudaFuncSetAttribute(gemm_fp16, cudaFuncAttributeMaxDynamicSharedMemorySize,
                         SMEM_BYTES);
    dim3 grid(N_DIM / BN, M / BM);    // (16, 128), x-fastest: qwh L2-resident
    gemm_fp16<<<grid, 256, SMEM_BYTES>>>(xh, qwh, y);
}

// round 13
// speedup vs baseline: 1.1121x; 1.1121x over previous
#include <cuda_runtime.h>
#include <cuda_fp16.h>
#include <cstdint>

#define K_DIM 4096
#define N_DIM 4096
#define BM 128
#define BN 128
#define BK 64                        // halfs of K per stage
#define KT (K_DIM / BK)              // 64
#define STAGES 3
#define SROWB 144                    // bytes per smem row (odd*16 -> LDSM conflict-free)
#define A_BYTES (BM * SROWB)         // 18432
#define B_BYTES (BN * SROWB)         // 18432
#define STAGE_BYTES (A_BYTES + B_BYTES)
#define SMEM_BYTES (STAGES * STAGE_BYTES)   // 110592

// device-global scratch (allocation-free)
__device__ __half g_qwh[(size_t)N_DIM * K_DIM];          // 32 MB
__device__ __half g_xh[(size_t)16384 * K_DIM];           // 128 MB

// ---------------------------------------------------------------------------
// Kernel 1: qw transform -> fp16
// ---------------------------------------------------------------------------
__global__ void qw_kernel(const float4* __restrict__ w,
                          const float* __restrict__ alpha,
                          const int4* __restrict__ wc,
                          __half2* __restrict__ out) {
    size_t i = (size_t)blockIdx.x * blockDim.x + threadIdx.x;
    const size_t n4 = (size_t)N_DIM * K_DIM / 4;
    if (i >= n4) return;
    const float a = alpha[0];
    const float decay = expf(-0.001f);
    float4 wv = w[i];
    int4 cv = wc[i];
    float wa[4] = {wv.x, wv.y, wv.z, wv.w};
    int ca[4] = {cv.x, cv.y, cv.z, cv.w};
    float r[4];
#pragma unroll
    for (int j = 0; j < 4; j++) {
        float tv = 4.5f * (1.0f + wa[j] * a);
        // nearest of {3.5,4.0,4.5,5.0,5.5}; tie -> lower index (argmin-first)
        int idx = (tv > 3.75f) + (tv > 4.25f) + (tv > 4.75f) + (tv > 5.25f);
        float qv = 3.5f + 0.5f * (float)idx;
        float q = (qv / 4.5f - 1.0f) / a;
        q *= decay;
        float d = (float)ca[j];
        d = d / 1e8f * 0.1f;
        d = fminf(fmaxf(d, 0.0f), 0.5f);
        r[j] = q * (1.0f - d);
    }
    out[i * 2]     = __floats2half2_rn(r[0], r[1]);
    out[i * 2 + 1] = __floats2half2_rn(r[2], r[3]);
}

// ---------------------------------------------------------------------------
// Kernel 2: x -> fp16
// ---------------------------------------------------------------------------
__global__ void xh_kernel(const float4* __restrict__ x, __half2* __restrict__ out,
                          size_t n4) {
    size_t i = (size_t)blockIdx.x * blockDim.x + threadIdx.x;
    if (i >= n4) return;
    float4 v = x[i];
    out[i * 2]     = __floats2half2_rn(v.x, v.y);
    out[i * 2 + 1] = __floats2half2_rn(v.z, v.w);
}

// ---------------------------------------------------------------------------
// Kernel 3: y[M,N] = xh[M,K] @ qwh[N,K]^T   fp16 mma.sync m16n8k16
// 128x128 CTA tile, 128 threads (4 warps of 64x64), 3-stage BK=64, 2 CTAs/SM
// ---------------------------------------------------------------------------
__device__ __forceinline__ void ldsm4(uint32_t* r, uint32_t addr) {
    asm volatile("ldmatrix.sync.aligned.m8n8.x4.shared.b16 {%0,%1,%2,%3}, [%4];"
                 : "=r"(r[0]), "=r"(r[1]), "=r"(r[2]), "=r"(r[3]) : "r"(addr));
}

__global__ __launch_bounds__(128, 2)
void gemm_fp16(const __half* __restrict__ A, const __half* __restrict__ B,
               float* __restrict__ Y) {
    extern __shared__ char smem[];
    const uint32_t sbase = (uint32_t)__cvta_generic_to_shared(smem);
    const int tid   = threadIdx.x;
    const int lane  = tid & 31;
    const int warp  = tid >> 5;
    const int warpM = warp >> 1;          // 0..1 -> 64-row band
    const int warpN = warp & 1;           // 0..1 -> 64-col band
    const int mBase = blockIdx.y * BM;
    const int nBase = blockIdx.x * BN;

    const __half* gA = A + (size_t)mBase * K_DIM;
    const __half* gB = B + (size_t)nBase * K_DIM;

    // cp.async mapping: 1024 chunks of 16B per matrix per stage; 8+8 per thread
    const int ldRow = tid >> 3;           // 0..15 (+16*i)
    const int ldC16 = tid & 7;            // 16B unit within 128B of row data

    // fragment base offsets (bytes within stage) — validated lane math
    const uint32_t aFrag = (uint32_t)((warpM * 64 + (lane & 15)) * SROWB
                                      + ((lane >> 4) & 1) * 16);
    const uint32_t bFrag = (uint32_t)(A_BYTES
                                      + (warpN * 64 + ((lane & 7) | ((lane >> 1) & 8))) * SROWB
                                      + ((lane >> 3) & 1) * 16);

    auto prefetch = [&](int t) {
        if (t < KT) {
            const uint32_t s = sbase + (t % STAGES) * STAGE_BYTES;
            const __half* gAk = gA + t * BK;
            const __half* gBk = gB + t * BK;
#pragma unroll
            for (int i = 0; i < 8; i++) {
                int row = ldRow + i * 16;
                asm volatile("cp.async.cg.shared.global [%0], [%1], 16;"
                             :: "r"(s + row * SROWB + ldC16 * 16),
                                "l"((const char*)(gAk + (size_t)row * K_DIM) + ldC16 * 16));
            }
#pragma unroll
            for (int i = 0; i < 8; i++) {
                int row = ldRow + i * 16;
                asm volatile("cp.async.cg.shared.global [%0], [%1], 16;"
                             :: "r"(s + A_BYTES + row * SROWB + ldC16 * 16),
                                "l"((const char*)(gBk + (size_t)row * K_DIM) + ldC16 * 16));
            }
        }
        asm volatile("cp.async.commit_group;");
    };

    float c[4][8][4];
#pragma unroll
    for (int i = 0; i < 4; i++)
#pragma unroll
        for (int j = 0; j < 8; j++)
#pragma unroll
            for (int r = 0; r < 4; r++) c[i][j][r] = 0.0f;

    prefetch(0); prefetch(1);

    for (int kt = 0; kt < KT; kt++) {
        asm volatile("cp.async.wait_group 1;");
        __syncthreads();
        prefetch(kt + 2);

        const uint32_t s = sbase + (kt % STAGES) * STAGE_BYTES;
#pragma unroll
        for (int ks = 0; ks < 4; ks++) {
            const uint32_t kb = ks * 32;        // 16 halves of K per step
            uint32_t a[4][4], b[4][4];
#pragma unroll
            for (int mt = 0; mt < 4; mt++)
                ldsm4(a[mt], s + aFrag + mt * (16 * SROWB) + kb);
#pragma unroll
            for (int np = 0; np < 4; np++)
                ldsm4(b[np], s + bFrag + np * (16 * SROWB) + kb);
#pragma unroll
            for (int mt = 0; mt < 4; mt++)
#pragma unroll
                for (int nt = 0; nt < 8; nt++) {
                    uint32_t b0 = b[nt >> 1][(nt & 1) * 2];
                    uint32_t b1 = b[nt >> 1][(nt & 1) * 2 + 1];
                    asm volatile(
                        "mma.sync.aligned.m16n8k16.row.col.f32.f16.f16.f32 "
                        "{%0,%1,%2,%3}, {%4,%5,%6,%7}, {%8,%9}, {%0,%1,%2,%3};"
                        : "+f"(c[mt][nt][0]), "+f"(c[mt][nt][1]),
                          "+f"(c[mt][nt][2]), "+f"(c[mt][nt][3])
                        : "r"(a[mt][0]), "r"(a[mt][1]), "r"(a[mt][2]), "r"(a[mt][3]),
                          "r"(b0), "r"(b1));
                }
        }
    }

    // epilogue
#pragma unroll
    for (int mt = 0; mt < 4; mt++) {
        const int r0 = mBase + warpM * 64 + mt * 16 + (lane >> 2);
#pragma unroll
        for (int nt = 0; nt < 8; nt++) {
            const int col = nBase + warpN * 64 + nt * 8 + (lane & 3) * 2;
            *(float2*)(Y + (size_t)r0 * N_DIM + col) =
                make_float2(c[mt][nt][0], c[mt][nt][1]);
            *(float2*)(Y + (size_t)(r0 + 8) * N_DIM + col) =
                make_float2(c[mt][nt][2], c[mt][nt][3]);
        }
    }
}

// ---------------------------------------------------------------------------
// Launch
// ---------------------------------------------------------------------------
extern "C" void kernel_launch(void* const* d_in, const int* in_sizes, int n_in,
                              void* d_out, int out_size) {
    const float* x     = (const float*)d_in[0];   // [8,2048,4096] fp32
    const float* w     = (const float*)d_in[1];   // [4096,4096] fp32
    const float* alpha = (const float*)d_in[2];   // [1] fp32
    const int*   wc    = (const int*)d_in[3];     // [4096,4096] int32
    float*       y     = (float*)d_out;           // [8,2048,4096] fp32

    const int M = in_sizes[0] / K_DIM;            // 16384

    __half *qwh = nullptr, *xh = nullptr;
    cudaGetSymbolAddress((void**)&qwh, g_qwh);
    cudaGetSymbolAddress((void**)&xh, g_xh);

    {   // qw transform -> fp16
        const size_t n4 = (size_t)N_DIM * K_DIM / 4;
        qw_kernel<<<(int)((n4 + 255) / 256), 256>>>(
            (const float4*)w, alpha, (const int4*)wc, (__half2*)qwh);
    }
    {   // x -> fp16
        const size_t n4 = (size_t)M * K_DIM / 4;
        xh_kernel<<<(int)((n4 + 255) / 256), 256>>>(
            (const float4*)x, (__half2*)xh, n4);
    }

    cudaFuncSetAttribute(gemm_fp16, cudaFuncAttributeMaxDynamicSharedMemorySize,
                         SMEM_BYTES);
    dim3 grid(N_DIM / BN, M / BM);    // (32, 128), x-fastest: qwh (32MB) L2-resident
    gemm_fp16<<<grid, 128, SMEM_BYTES>>>(xh, qwh, y);
}

// round 16
// speedup vs baseline: 1.1326x; 1.0185x over previous
#include <cuda_runtime.h>
#include <cuda_fp16.h>
#include <cstdint>

#define K_DIM 4096
#define N_DIM 4096
#define BM 128
#define BN 128
#define BK 64                        // halfs of K per stage
#define KT (K_DIM / BK)              // 64
#define STAGES 3
#define SROWB 144                    // bytes per smem row (odd*16 -> LDSM conflict-free)
#define A_BYTES (BM * SROWB)         // 18432
#define B_BYTES (BN * SROWB)         // 18432
#define STAGE_BYTES (A_BYTES + B_BYTES)
#define SMEM_BYTES (STAGES * STAGE_BYTES)   // 110592

// device-global scratch (allocation-free)
__device__ __half g_qwh[(size_t)N_DIM * K_DIM];          // 32 MB
__device__ __half g_xh[(size_t)16384 * K_DIM];           // 128 MB

// ---------------------------------------------------------------------------
// Fused prep kernel: blocks [0, QW_BLOCKS) transform weight -> fp16,
// remaining blocks convert x -> fp16. Independent work runs concurrently.
// ---------------------------------------------------------------------------
#define QW_BLOCKS 16384

__global__ void prep_kernel(const float4* __restrict__ w,
                            const float* __restrict__ alpha,
                            const int4* __restrict__ wc,
                            __half2* __restrict__ qwh,
                            const float4* __restrict__ x,
                            __half2* __restrict__ xh,
                            size_t xh_n4) {
    const int bid = blockIdx.x;
    if (bid < QW_BLOCKS) {
        size_t i = (size_t)bid * blockDim.x + threadIdx.x;
        const size_t n4 = (size_t)N_DIM * K_DIM / 4;
        if (i >= n4) return;
        const float a = alpha[0];
        const float scale = expf(-0.001f) / (4.5f * a);   // (qv-4.5)*scale == decayed qw
        float4 wv = w[i];
        int4 cv = wc[i];
        float wa[4] = {wv.x, wv.y, wv.z, wv.w};
        int ca[4] = {cv.x, cv.y, cv.z, cv.w};
        float r[4];
#pragma unroll
        for (int j = 0; j < 4; j++) {
            float tv = 4.5f * (1.0f + wa[j] * a);
            // nearest of {3.5,4.0,4.5,5.0,5.5}; tie -> lower index (argmin-first)
            int idx = (tv > 3.75f) + (tv > 4.25f) + (tv > 4.75f) + (tv > 5.25f);
            float qv = 3.5f + 0.5f * (float)idx;
            float q = (qv - 4.5f) * scale;
            float d = (float)ca[j] * 1e-9f;
            d = fminf(fmaxf(d, 0.0f), 0.5f);
            r[j] = q * (1.0f - d);
        }
        qwh[i * 2]     = __floats2half2_rn(r[0], r[1]);
        qwh[i * 2 + 1] = __floats2half2_rn(r[2], r[3]);
    } else {
        size_t i = (size_t)(bid - QW_BLOCKS) * blockDim.x + threadIdx.x;
        if (i >= xh_n4) return;
        float4 v = x[i];
        xh[i * 2]     = __floats2half2_rn(v.x, v.y);
        xh[i * 2 + 1] = __floats2half2_rn(v.z, v.w);
    }
}

// ---------------------------------------------------------------------------
// GEMM: y[M,N] = xh[M,K] @ qwh[N,K]^T   fp16 mma.sync m16n8k16
// 128x128 CTA tile, 128 threads (4 warps of 64x64), 3-stage BK=64, 2 CTAs/SM
// ks-loop software-pipelined with double-buffered fragments
// ---------------------------------------------------------------------------
__device__ __forceinline__ void ldsm4(uint32_t* r, uint32_t addr) {
    asm volatile("ldmatrix.sync.aligned.m8n8.x4.shared.b16 {%0,%1,%2,%3}, [%4];"
                 : "=r"(r[0]), "=r"(r[1]), "=r"(r[2]), "=r"(r[3]) : "r"(addr));
}

__global__ __launch_bounds__(128, 2)
void gemm_fp16(const __half* __restrict__ A, const __half* __restrict__ B,
               float* __restrict__ Y) {
    extern __shared__ char smem[];
    const uint32_t sbase = (uint32_t)__cvta_generic_to_shared(smem);
    const int tid   = threadIdx.x;
    const int lane  = tid & 31;
    const int warp  = tid >> 5;
    const int warpM = warp >> 1;          // 0..1 -> 64-row band
    const int warpN = warp & 1;           // 0..1 -> 64-col band
    const int mBase = blockIdx.y * BM;
    const int nBase = blockIdx.x * BN;

    const __half* gA = A + (size_t)mBase * K_DIM;
    const __half* gB = B + (size_t)nBase * K_DIM;

    // cp.async mapping: 1024 chunks of 16B per matrix per stage; 8+8 per thread
    const int ldRow = tid >> 3;           // 0..15 (+16*i)
    const int ldC16 = tid & 7;            // 16B unit within 128B of row data

    // fragment base offsets (bytes within stage) — validated lane math
    const uint32_t aFrag = (uint32_t)((warpM * 64 + (lane & 15)) * SROWB
                                      + ((lane >> 4) & 1) * 16);
    const uint32_t bFrag = (uint32_t)(A_BYTES
                                      + (warpN * 64 + ((lane & 7) | ((lane >> 1) & 8))) * SROWB
                                      + ((lane >> 3) & 1) * 16);

    auto prefetch = [&](int t) {
        if (t < KT) {
            const uint32_t s = sbase + (t % STAGES) * STAGE_BYTES;
            const __half* gAk = gA + t * BK;
            const __half* gBk = gB + t * BK;
#pragma unroll
            for (int i = 0; i < 8; i++) {
                int row = ldRow + i * 16;
                asm volatile("cp.async.cg.shared.global [%0], [%1], 16;"
                             :: "r"(s + row * SROWB + ldC16 * 16),
                                "l"((const char*)(gAk + (size_t)row * K_DIM) + ldC16 * 16));
            }
#pragma unroll
            for (int i = 0; i < 8; i++) {
                int row = ldRow + i * 16;
                asm volatile("cp.async.cg.shared.global [%0], [%1], 16;"
                             :: "r"(s + A_BYTES + row * SROWB + ldC16 * 16),
                                "l"((const char*)(gBk + (size_t)row * K_DIM) + ldC16 * 16));
            }
        }
        asm volatile("cp.async.commit_group;");
    };

    float c[4][8][4];
#pragma unroll
    for (int i = 0; i < 4; i++)
#pragma unroll
        for (int j = 0; j < 8; j++)
#pragma unroll
            for (int r = 0; r < 4; r++) c[i][j][r] = 0.0f;

    uint32_t a[2][4][4], b[2][4][4];

    prefetch(0); prefetch(1);

    for (int kt = 0; kt < KT; kt++) {
        asm volatile("cp.async.wait_group 1;");
        __syncthreads();
        prefetch(kt + 2);

        const uint32_t s = sbase + (kt % STAGES) * STAGE_BYTES;

        // load ks=0 fragments
#pragma unroll
        for (int mt = 0; mt < 4; mt++)
            ldsm4(a[0][mt], s + aFrag + mt * (16 * SROWB));
#pragma unroll
        for (int np = 0; np < 4; np++)
            ldsm4(b[0][np], s + bFrag + np * (16 * SROWB));

#pragma unroll
        for (int ks = 0; ks < 4; ks++) {
            const int cur = ks & 1;
            const int nxt = cur ^ 1;
            // prefetch frags for ks+1 while HMMAs for ks issue below
            if (ks < 3) {
                const uint32_t kb = (ks + 1) * 32;
#pragma unroll
                for (int mt = 0; mt < 4; mt++)
                    ldsm4(a[nxt][mt], s + aFrag + mt * (16 * SROWB) + kb);
#pragma unroll
                for (int np = 0; np < 4; np++)
                    ldsm4(b[nxt][np], s + bFrag + np * (16 * SROWB) + kb);
            }
#pragma unroll
            for (int mt = 0; mt < 4; mt++)
#pragma unroll
                for (int nt = 0; nt < 8; nt++) {
                    uint32_t b0 = b[cur][nt >> 1][(nt & 1) * 2];
                    uint32_t b1 = b[cur][nt >> 1][(nt & 1) * 2 + 1];
                    asm volatile(
                        "mma.sync.aligned.m16n8k16.row.col.f32.f16.f16.f32 "
                        "{%0,%1,%2,%3}, {%4,%5,%6,%7}, {%8,%9}, {%0,%1,%2,%3};"
                        : "+f"(c[mt][nt][0]), "+f"(c[mt][nt][1]),
                          "+f"(c[mt][nt][2]), "+f"(c[mt][nt][3])
                        : "r"(a[cur][mt][0]), "r"(a[cur][mt][1]),
                          "r"(a[cur][mt][2]), "r"(a[cur][mt][3]),
                          "r"(b0), "r"(b1));
                }
        }
    }

    // epilogue
#pragma unroll
    for (int mt = 0; mt < 4; mt++) {
        const int r0 = mBase + warpM * 64 + mt * 16 + (lane >> 2);
#pragma unroll
        for (int nt = 0; nt < 8; nt++) {
            const int col = nBase + warpN * 64 + nt * 8 + (lane & 3) * 2;
            *(float2*)(Y + (size_t)r0 * N_DIM + col) =
                make_float2(c[mt][nt][0], c[mt][nt][1]);
            *(float2*)(Y + (size_t)(r0 + 8) * N_DIM + col) =
                make_float2(c[mt][nt][2], c[mt][nt][3]);
        }
    }
}

// ---------------------------------------------------------------------------
// Launch
// ---------------------------------------------------------------------------
extern "C" void kernel_launch(void* const* d_in, const int* in_sizes, int n_in,
                              void* d_out, int out_size) {
    const float* x     = (const float*)d_in[0];   // [8,2048,4096] fp32
    const float* w     = (const float*)d_in[1];   // [4096,4096] fp32
    const float* alpha = (const float*)d_in[2];   // [1] fp32
    const int*   wc    = (const int*)d_in[3];     // [4096,4096] int32
    float*       y     = (float*)d_out;           // [8,2048,4096] fp32

    const int M = in_sizes[0] / K_DIM;            // 16384

    __half *qwh = nullptr, *xh = nullptr;
    cudaGetSymbolAddress((void**)&qwh, g_qwh);
    cudaGetSymbolAddress((void**)&xh, g_xh);

    {   // fused prep: qw transform + x conversion (concurrent inside one launch)
        const size_t xn4 = (size_t)M * K_DIM / 4;
        const int xblocks = (int)((xn4 + 255) / 256);
        prep_kernel<<<QW_BLOCKS + xblocks, 256>>>(
            (const float4*)w, alpha, (const int4*)wc, (__half2*)qwh,
            (const float4*)x, (__half2*)xh, xn4);
    }

    cudaFuncSetAttribute(gemm_fp16, cudaFuncAttributeMaxDynamicSharedMemorySize,
                         SMEM_BYTES);
    dim3 grid(N_DIM / BN, M / BM);    // (32, 128), x-fastest: qwh (32MB) L2-resident
    gemm_fp16<<<grid, 128, SMEM_BYTES>>>(xh, qwh, y);
}

// round 17
// speedup vs baseline: 1.1900x; 1.0506x over previous
#include <cuda_runtime.h>
#include <cuda_fp16.h>
#include <cstdint>

#define K_DIM 4096
#define N_DIM 4096
#define BM 128
#define BN 64
#define BK 64                        // halfs of K per stage
#define KT (K_DIM / BK)              // 64
#define STAGES 2
#define SROWB 144                    // bytes per smem row (odd*16 -> LDSM conflict-free)
#define A_BYTES (BM * SROWB)         // 18432
#define B_BYTES (BN * SROWB)         // 9216
#define STAGE_BYTES (A_BYTES + B_BYTES)
#define SMEM_BYTES (STAGES * STAGE_BYTES)   // 55296

// device-global scratch (allocation-free)
__device__ __half g_qwh[(size_t)N_DIM * K_DIM];          // 32 MB
__device__ __half g_xh[(size_t)16384 * K_DIM];           // 128 MB

// ---------------------------------------------------------------------------
// Fused prep kernel: blocks [0, QW_BLOCKS) transform weight -> fp16,
// remaining blocks convert x -> fp16. Independent work runs concurrently.
// ---------------------------------------------------------------------------
#define QW_BLOCKS 16384

__global__ void prep_kernel(const float4* __restrict__ w,
                            const float* __restrict__ alpha,
                            const int4* __restrict__ wc,
                            __half2* __restrict__ qwh,
                            const float4* __restrict__ x,
                            __half2* __restrict__ xh,
                            size_t xh_n4) {
    const int bid = blockIdx.x;
    if (bid < QW_BLOCKS) {
        size_t i = (size_t)bid * blockDim.x + threadIdx.x;
        const size_t n4 = (size_t)N_DIM * K_DIM / 4;
        if (i >= n4) return;
        const float a = alpha[0];
        const float scale = expf(-0.001f) / (4.5f * a);   // (qv-4.5)*scale == decayed qw
        float4 wv = w[i];
        int4 cv = wc[i];
        float wa[4] = {wv.x, wv.y, wv.z, wv.w};
        int ca[4] = {cv.x, cv.y, cv.z, cv.w};
        float r[4];
#pragma unroll
        for (int j = 0; j < 4; j++) {
            float tv = 4.5f * (1.0f + wa[j] * a);
            // nearest of {3.5,4.0,4.5,5.0,5.5}; tie -> lower index (argmin-first)
            int idx = (tv > 3.75f) + (tv > 4.25f) + (tv > 4.75f) + (tv > 5.25f);
            float qv = 3.5f + 0.5f * (float)idx;
            float q = (qv - 4.5f) * scale;
            float d = fminf((float)ca[j] * 1e-9f, 0.5f);   // wc >= 0: no lower clip needed
            r[j] = q * (1.0f - d);
        }
        qwh[i * 2]     = __floats2half2_rn(r[0], r[1]);
        qwh[i * 2 + 1] = __floats2half2_rn(r[2], r[3]);
    } else {
        size_t i = (size_t)(bid - QW_BLOCKS) * blockDim.x + threadIdx.x;
        if (i >= xh_n4) return;
        float4 v = x[i];
        xh[i * 2]     = __floats2half2_rn(v.x, v.y);
        xh[i * 2 + 1] = __floats2half2_rn(v.z, v.w);
    }
}

// ---------------------------------------------------------------------------
// GEMM: y[M,N] = xh[M,K] @ qwh[N,K]^T   fp16 mma.sync m16n8k16
// 128x64 CTA tile, 128 threads (4 warps of 64x32), 2-stage BK=64, 4 CTAs/SM
// ---------------------------------------------------------------------------
__device__ __forceinline__ void ldsm4(uint32_t* r, uint32_t addr) {
    asm volatile("ldmatrix.sync.aligned.m8n8.x4.shared.b16 {%0,%1,%2,%3}, [%4];"
                 : "=r"(r[0]), "=r"(r[1]), "=r"(r[2]), "=r"(r[3]) : "r"(addr));
}

__global__ __launch_bounds__(128, 4)
void gemm_fp16(const __half* __restrict__ A, const __half* __restrict__ B,
               float* __restrict__ Y) {
    extern __shared__ char smem[];
    const uint32_t sbase = (uint32_t)__cvta_generic_to_shared(smem);
    const int tid   = threadIdx.x;
    const int lane  = tid & 31;
    const int warp  = tid >> 5;
    const int warpM = warp >> 1;          // 0..1 -> 64-row band
    const int warpN = warp & 1;           // 0..1 -> 32-col band
    const int mBase = blockIdx.y * BM;
    const int nBase = blockIdx.x * BN;

    const __half* gA = A + (size_t)mBase * K_DIM;
    const __half* gB = B + (size_t)nBase * K_DIM;

    // cp.async mapping: A 1024 + B 512 chunks of 16B per stage; 8+4 per thread
    const int ldRow = tid >> 3;           // 0..15 (+16*i)
    const int ldC16 = tid & 7;            // 16B unit within 128B of row data

    // fragment base offsets (bytes within stage) — validated lane math
    const uint32_t aFrag = (uint32_t)((warpM * 64 + (lane & 15)) * SROWB
                                      + ((lane >> 4) & 1) * 16);
    const uint32_t bFrag = (uint32_t)(A_BYTES
                                      + (warpN * 32 + ((lane & 7) | ((lane >> 1) & 8))) * SROWB
                                      + ((lane >> 3) & 1) * 16);

    auto prefetch = [&](int t) {
        if (t < KT) {
            const uint32_t s = sbase + (t & 1) * STAGE_BYTES;
            const __half* gAk = gA + t * BK;
            const __half* gBk = gB + t * BK;
#pragma unroll
            for (int i = 0; i < 8; i++) {
                int row = ldRow + i * 16;
                asm volatile("cp.async.cg.shared.global [%0], [%1], 16;"
                             :: "r"(s + row * SROWB + ldC16 * 16),
                                "l"((const char*)(gAk + (size_t)row * K_DIM) + ldC16 * 16));
            }
#pragma unroll
            for (int i = 0; i < 4; i++) {
                int row = ldRow + i * 16;
                asm volatile("cp.async.cg.shared.global [%0], [%1], 16;"
                             :: "r"(s + A_BYTES + row * SROWB + ldC16 * 16),
                                "l"((const char*)(gBk + (size_t)row * K_DIM) + ldC16 * 16));
            }
        }
        asm volatile("cp.async.commit_group;");
    };

    float c[4][4][4];
#pragma unroll
    for (int i = 0; i < 4; i++)
#pragma unroll
        for (int j = 0; j < 4; j++)
#pragma unroll
            for (int r = 0; r < 4; r++) c[i][j][r] = 0.0f;

    prefetch(0);

    for (int kt = 0; kt < KT; kt++) {
        asm volatile("cp.async.wait_group 0;");   // stage (kt&1) data resident
        __syncthreads();                          // all warps done reading stage (kt-1)&1
        prefetch(kt + 1);                         // safe: overwrites stage ((kt+1)&1) = (kt-1)&1

        const uint32_t s = sbase + (kt & 1) * STAGE_BYTES;
#pragma unroll
        for (int ks = 0; ks < 4; ks++) {
            const uint32_t kb = ks * 32;          // 16 halves of K per step
            uint32_t a[4][4], b[2][4];
#pragma unroll
            for (int mt = 0; mt < 4; mt++)
                ldsm4(a[mt], s + aFrag + mt * (16 * SROWB) + kb);
#pragma unroll
            for (int np = 0; np < 2; np++)
                ldsm4(b[np], s + bFrag + np * (16 * SROWB) + kb);
#pragma unroll
            for (int mt = 0; mt < 4; mt++)
#pragma unroll
                for (int nt = 0; nt < 4; nt++) {
                    uint32_t b0 = b[nt >> 1][(nt & 1) * 2];
                    uint32_t b1 = b[nt >> 1][(nt & 1) * 2 + 1];
                    asm volatile(
                        "mma.sync.aligned.m16n8k16.row.col.f32.f16.f16.f32 "
                        "{%0,%1,%2,%3}, {%4,%5,%6,%7}, {%8,%9}, {%0,%1,%2,%3};"
                        : "+f"(c[mt][nt][0]), "+f"(c[mt][nt][1]),
                          "+f"(c[mt][nt][2]), "+f"(c[mt][nt][3])
                        : "r"(a[mt][0]), "r"(a[mt][1]), "r"(a[mt][2]), "r"(a[mt][3]),
                          "r"(b0), "r"(b1));
                }
        }
    }

    // epilogue
#pragma unroll
    for (int mt = 0; mt < 4; mt++) {
        const int r0 = mBase + warpM * 64 + mt * 16 + (lane >> 2);
#pragma unroll
        for (int nt = 0; nt < 4; nt++) {
            const int col = nBase + warpN * 32 + nt * 8 + (lane & 3) * 2;
            *(float2*)(Y + (size_t)r0 * N_DIM + col) =
                make_float2(c[mt][nt][0], c[mt][nt][1]);
            *(float2*)(Y + (size_t)(r0 + 8) * N_DIM + col) =
                make_float2(c[mt][nt][2], c[mt][nt][3]);
        }
    }
}

// ---------------------------------------------------------------------------
// Launch
// ---------------------------------------------------------------------------
extern "C" void kernel_launch(void* const* d_in, const int* in_sizes, int n_in,
                              void* d_out, int out_size) {
    const float* x     = (const float*)d_in[0];   // [8,2048,4096] fp32
    const float* w     = (const float*)d_in[1];   // [4096,4096] fp32
    const float* alpha = (const float*)d_in[2];   // [1] fp32
    const int*   wc    = (const int*)d_in[3];     // [4096,4096] int32
    float*       y     = (float*)d_out;           // [8,2048,4096] fp32

    const int M = in_sizes[0] / K_DIM;            // 16384

    __half *qwh = nullptr, *xh = nullptr;
    cudaGetSymbolAddress((void**)&qwh, g_qwh);
    cudaGetSymbolAddress((void**)&xh, g_xh);

    {   // fused prep: qw transform + x conversion (concurrent inside one launch)
        const size_t xn4 = (size_t)M * K_DIM / 4;
        const int xblocks = (int)((xn4 + 255) / 256);
        prep_kernel<<<QW_BLOCKS + xblocks, 256>>>(
            (const float4*)w, alpha, (const int4*)wc, (__half2*)qwh,
            (const float4*)x, (__half2*)xh, xn4);
    }

    cudaFuncSetAttribute(gemm_fp16, cudaFuncAttributeMaxDynamicSharedMemorySize,
                         SMEM_BYTES);
    dim3 grid(N_DIM / BN, M / BM);    // (64, 128), x-fastest: qwh (32MB) L2-resident
    gemm_fp16<<<grid, 128, SMEM_BYTES>>>(xh, qwh, y);
}